// round 1
// baseline (speedup 1.0000x reference)
#include <cuda_runtime.h>
#include <math.h>

#define N_NODES 100000
#define N_EDGES 1600000
#define IN_F    256
#define NHEAD   4
#define DHID    32
#define NCLS    47
#define F1      128    // NHEAD*DHID
#define F3      188    // NHEAD*NCLS
#define NEG_SLOPE 0.2f

// ---------------- scratch (no allocs allowed) ----------------
__device__ float g_feat[(size_t)N_NODES * F3];   // GEMM output (max 188 cols)
__device__ float g_h[(size_t)N_NODES * F1];      // aggregated hidden (layers 1,2)
__device__ float g_out3[(size_t)N_NODES * F3];   // layer-3 aggregated output
__device__ float g_el[N_NODES * NHEAD];
__device__ float g_er[N_NODES * NHEAD];
__device__ float g_m[N_NODES * NHEAD];
__device__ float g_invden[N_NODES * NHEAD];
__device__ int   g_rowptr[N_NODES + 1];
__device__ int   g_cnt[N_NODES];
__device__ int   g_csr_src[N_EDGES];

// ---------------- CSR build ----------------
__global__ void zero_cnt_kernel() {
    int i = blockIdx.x * blockDim.x + threadIdx.x;
    if (i < N_NODES) g_cnt[i] = 0;
}

__global__ void hist_kernel(const int* __restrict__ dst) {
    int e = blockIdx.x * blockDim.x + threadIdx.x;
    if (e < N_EDGES) atomicAdd(&g_cnt[dst[e]], 1);
}

// single block, 1024 threads: chunked exclusive scan of g_cnt -> g_rowptr
__global__ void scan_kernel() {
    __shared__ int ssum[1024];
    int t = threadIdx.x;
    const int CH = (N_NODES + 1023) / 1024;  // 98
    int lo = t * CH;
    int hi = lo + CH; if (hi > N_NODES) hi = N_NODES;
    if (lo > N_NODES) lo = N_NODES;
    int s = 0;
    for (int i = lo; i < hi; i++) s += g_cnt[i];
    ssum[t] = s;
    __syncthreads();
    // Hillis-Steele inclusive scan
    for (int off = 1; off < 1024; off <<= 1) {
        int add = (t >= off) ? ssum[t - off] : 0;
        __syncthreads();
        ssum[t] += add;
        __syncthreads();
    }
    int base = (t > 0) ? ssum[t - 1] : 0;
    for (int i = lo; i < hi; i++) {
        int d = g_cnt[i];
        g_rowptr[i] = base;
        base += d;
    }
    if (t == 1023) g_rowptr[N_NODES] = ssum[1023];  // == N_EDGES
}

__global__ void place_kernel(const int* __restrict__ src, const int* __restrict__ dst) {
    int e = blockIdx.x * blockDim.x + threadIdx.x;
    if (e < N_EDGES) {
        int d = dst[e];
        int slot = g_rowptr[d] + atomicAdd(&g_cnt[d], 1);
        g_csr_src[slot] = src[e];
    }
}

// ---------------- SGEMM: C[M,Ncols] = A[M,K] @ B[K,Ncols] ----------------
// BM=BN=64, BK=16, 256 threads, 4x4 microtile
__global__ __launch_bounds__(256) void sgemm_kernel(
    const float* __restrict__ A, const float* __restrict__ B,
    float* __restrict__ C, int M, int K, int Ncols)
{
    __shared__ float As[16][64];
    __shared__ float Bs[16][64];
    int tid = threadIdx.x;
    int ty = tid >> 4;          // 0..15 -> row group
    int tx = tid & 15;          // 0..15 -> col group
    int rowBase = blockIdx.y * 64;
    int colBase = blockIdx.x * 64;

    float acc[4][4];
#pragma unroll
    for (int i = 0; i < 4; i++)
#pragma unroll
        for (int j = 0; j < 4; j++) acc[i][j] = 0.f;

    // A tile load mapping: one float4 along K
    int ar = tid >> 2;            // 0..63 row within tile
    int ac = (tid & 3) * 4;       // 0,4,8,12 k offset
    // B tile load mapping: one float4 along N
    int br = tid >> 4;            // 0..15 k row
    int bc = (tid & 15) * 4;      // 0..60 col offset

    for (int kk = 0; kk < K; kk += 16) {
        int grow = rowBase + ar;
        float4 a4 = make_float4(0.f, 0.f, 0.f, 0.f);
        if (grow < M) a4 = *(const float4*)(A + (size_t)grow * K + kk + ac);
        As[ac + 0][ar] = a4.x;
        As[ac + 1][ar] = a4.y;
        As[ac + 2][ar] = a4.z;
        As[ac + 3][ar] = a4.w;

        int gcol = colBase + bc;
        float4 b4 = make_float4(0.f, 0.f, 0.f, 0.f);
        if (gcol < Ncols) b4 = *(const float4*)(B + (size_t)(kk + br) * Ncols + gcol);
        *(float4*)&Bs[br][bc] = b4;

        __syncthreads();
#pragma unroll
        for (int k = 0; k < 16; k++) {
            float4 a = *(float4*)&As[k][ty * 4];
            float4 b = *(float4*)&Bs[k][tx * 4];
            acc[0][0] += a.x * b.x; acc[0][1] += a.x * b.y; acc[0][2] += a.x * b.z; acc[0][3] += a.x * b.w;
            acc[1][0] += a.y * b.x; acc[1][1] += a.y * b.y; acc[1][2] += a.y * b.z; acc[1][3] += a.y * b.w;
            acc[2][0] += a.z * b.x; acc[2][1] += a.z * b.y; acc[2][2] += a.z * b.z; acc[2][3] += a.z * b.w;
            acc[3][0] += a.w * b.x; acc[3][1] += a.w * b.y; acc[3][2] += a.w * b.z; acc[3][3] += a.w * b.w;
        }
        __syncthreads();
    }

#pragma unroll
    for (int i = 0; i < 4; i++) {
        int r = rowBase + ty * 4 + i;
        if (r >= M) continue;
        int c = colBase + tx * 4;
        if (c < Ncols) {  // Ncols % 4 == 0 always here
            float4 v = make_float4(acc[i][0], acc[i][1], acc[i][2], acc[i][3]);
            *(float4*)(C + (size_t)r * Ncols + c) = v;
        }
    }
}

// ---------------- el/er: warp per node ----------------
__global__ void elr_kernel(const float* __restrict__ al, const float* __restrict__ ar,
                           int Dl, int F)
{
    int warp = (blockIdx.x * blockDim.x + threadIdx.x) >> 5;
    int lane = threadIdx.x & 31;
    if (warp >= N_NODES) return;
    const float* frow = g_feat + (size_t)warp * F;
#pragma unroll
    for (int h = 0; h < NHEAD; h++) {
        float sl = 0.f, sr = 0.f;
        for (int d = lane; d < Dl; d += 32) {
            float v = frow[h * Dl + d];
            sl += v * al[h * Dl + d];
            sr += v * ar[h * Dl + d];
        }
#pragma unroll
        for (int off = 16; off > 0; off >>= 1) {
            sl += __shfl_xor_sync(0xffffffffu, sl, off);
            sr += __shfl_xor_sync(0xffffffffu, sr, off);
        }
        if (lane == 0) {
            g_el[warp * NHEAD + h] = sl;
            g_er[warp * NHEAD + h] = sr;
        }
    }
}

__device__ __forceinline__ float leaky(float x) {
    return x > 0.f ? x : NEG_SLOPE * x;
}

// ---------------- segment max + sum(exp): warp per node ----------------
__global__ void mden_kernel() {
    int v = (blockIdx.x * blockDim.x + threadIdx.x) >> 5;
    int lane = threadIdx.x & 31;
    if (v >= N_NODES) return;
    int start = g_rowptr[v];
    int end   = g_rowptr[v + 1];
    float4 erv = *(const float4*)&g_er[v * 4];

    float m0 = -INFINITY, m1 = -INFINITY, m2 = -INFINITY, m3 = -INFINITY;
    for (int j = start + lane; j < end; j += 32) {
        int u = g_csr_src[j];
        float4 elu = *(const float4*)&g_el[u * 4];
        m0 = fmaxf(m0, leaky(elu.x + erv.x));
        m1 = fmaxf(m1, leaky(elu.y + erv.y));
        m2 = fmaxf(m2, leaky(elu.z + erv.z));
        m3 = fmaxf(m3, leaky(elu.w + erv.w));
    }
#pragma unroll
    for (int off = 16; off > 0; off >>= 1) {
        m0 = fmaxf(m0, __shfl_xor_sync(0xffffffffu, m0, off));
        m1 = fmaxf(m1, __shfl_xor_sync(0xffffffffu, m1, off));
        m2 = fmaxf(m2, __shfl_xor_sync(0xffffffffu, m2, off));
        m3 = fmaxf(m3, __shfl_xor_sync(0xffffffffu, m3, off));
    }
    float s0 = 0.f, s1 = 0.f, s2 = 0.f, s3 = 0.f;
    for (int j = start + lane; j < end; j += 32) {
        int u = g_csr_src[j];
        float4 elu = *(const float4*)&g_el[u * 4];
        s0 += __expf(leaky(elu.x + erv.x) - m0);
        s1 += __expf(leaky(elu.y + erv.y) - m1);
        s2 += __expf(leaky(elu.z + erv.z) - m2);
        s3 += __expf(leaky(elu.w + erv.w) - m3);
    }
#pragma unroll
    for (int off = 16; off > 0; off >>= 1) {
        s0 += __shfl_xor_sync(0xffffffffu, s0, off);
        s1 += __shfl_xor_sync(0xffffffffu, s1, off);
        s2 += __shfl_xor_sync(0xffffffffu, s2, off);
        s3 += __shfl_xor_sync(0xffffffffu, s3, off);
    }
    if (lane == 0) {
        *(float4*)&g_m[v * 4] = make_float4(m0, m1, m2, m3);
        float4 inv;
        inv.x = s0 > 0.f ? 1.f / s0 : 0.f;
        inv.y = s1 > 0.f ? 1.f / s1 : 0.f;
        inv.z = s2 > 0.f ? 1.f / s2 : 0.f;
        inv.w = s3 > 0.f ? 1.f / s3 : 0.f;
        *(float4*)&g_invden[v * 4] = inv;
    }
}

// ---------------- aggregation, F=128 (D=32): warp per node ----------------
// lane owns features [4*lane, 4*lane+3]; head = lane>>3 (since D=32)
__global__ void agg128_kernel(const float* __restrict__ bias, float* __restrict__ out,
                              int do_relu)
{
    int v = (blockIdx.x * blockDim.x + threadIdx.x) >> 5;
    int lane = threadIdx.x & 31;
    if (v >= N_NODES) return;
    int start = g_rowptr[v];
    int end   = g_rowptr[v + 1];
    int h = lane >> 3;
    float erh = g_er[v * 4 + h];
    float mh  = g_m[v * 4 + h];
    float inv = g_invden[v * 4 + h];

    float4 acc = make_float4(0.f, 0.f, 0.f, 0.f);
    for (int j = start; j < end; j++) {
        int u = g_csr_src[j];                         // broadcast load
        float elh = g_el[u * 4 + h];                  // 4 distinct addrs / warp
        float a = __expf(leaky(elh + erh) - mh) * inv;
        float4 f = *(const float4*)(g_feat + (size_t)u * F1 + lane * 4);
        acc.x += a * f.x;
        acc.y += a * f.y;
        acc.z += a * f.z;
        acc.w += a * f.w;
    }
    float4 b4 = *(const float4*)(bias + lane * 4);
    acc.x += b4.x; acc.y += b4.y; acc.z += b4.z; acc.w += b4.w;
    if (do_relu) {
        acc.x = fmaxf(acc.x, 0.f); acc.y = fmaxf(acc.y, 0.f);
        acc.z = fmaxf(acc.z, 0.f); acc.w = fmaxf(acc.w, 0.f);
    }
    *(float4*)(out + (size_t)v * F1 + lane * 4) = acc;
}

__device__ __forceinline__ float pick4(float a0, float a1, float a2, float a3, int hh) {
    return hh == 0 ? a0 : (hh == 1 ? a1 : (hh == 2 ? a2 : a3));
}

// ---------------- aggregation, F=188 (C=47): warp per node ----------------
// lane owns [4*lane..4*lane+3] and (lane<15) [128+4*lane..128+4*lane+3]
__global__ void agg188_kernel(const float* __restrict__ bias, float* __restrict__ out)
{
    int v = (blockIdx.x * blockDim.x + threadIdx.x) >> 5;
    int lane = threadIdx.x & 31;
    if (v >= N_NODES) return;
    int start = g_rowptr[v];
    int end   = g_rowptr[v + 1];
    float4 erv = *(const float4*)&g_er[v * 4];
    float4 m4  = *(const float4*)&g_m[v * 4];
    float4 iv4 = *(const float4*)&g_invden[v * 4];

    int iA = lane * 4;           // 0..124
    int iB = 128 + lane * 4;     // 128..252 (valid if < 188)
    bool hasB = (iB + 3) < F3;   // lane < 15
    int hA0 = (iA + 0) / NCLS, hA1 = (iA + 1) / NCLS, hA2 = (iA + 2) / NCLS, hA3 = (iA + 3) / NCLS;
    int hB0 = (iB + 0) / NCLS, hB1 = (iB + 1) / NCLS, hB2 = (iB + 2) / NCLS, hB3 = (iB + 3) / NCLS;

    float4 accA = make_float4(0.f, 0.f, 0.f, 0.f);
    float4 accB = make_float4(0.f, 0.f, 0.f, 0.f);
    for (int j = start; j < end; j++) {
        int u = g_csr_src[j];
        float4 elu = *(const float4*)&g_el[u * 4];
        float a0 = __expf(leaky(elu.x + erv.x) - m4.x) * iv4.x;
        float a1 = __expf(leaky(elu.y + erv.y) - m4.y) * iv4.y;
        float a2 = __expf(leaky(elu.z + erv.z) - m4.z) * iv4.z;
        float a3 = __expf(leaky(elu.w + erv.w) - m4.w) * iv4.w;
        const float* frow = g_feat + (size_t)u * F3;
        float4 fA = *(const float4*)(frow + iA);
        accA.x += pick4(a0, a1, a2, a3, hA0) * fA.x;
        accA.y += pick4(a0, a1, a2, a3, hA1) * fA.y;
        accA.z += pick4(a0, a1, a2, a3, hA2) * fA.z;
        accA.w += pick4(a0, a1, a2, a3, hA3) * fA.w;
        if (hasB) {
            float4 fB = *(const float4*)(frow + iB);
            accB.x += pick4(a0, a1, a2, a3, hB0) * fB.x;
            accB.y += pick4(a0, a1, a2, a3, hB1) * fB.y;
            accB.z += pick4(a0, a1, a2, a3, hB2) * fB.z;
            accB.w += pick4(a0, a1, a2, a3, hB3) * fB.w;
        }
    }
    float* orow = out + (size_t)v * F3;
    float4 bA = *(const float4*)(bias + iA);
    accA.x += bA.x; accA.y += bA.y; accA.z += bA.z; accA.w += bA.w;
    *(float4*)(orow + iA) = accA;
    if (hasB) {
        float4 bB = *(const float4*)(bias + iB);
        accB.x += bB.x; accB.y += bB.y; accB.z += bB.z; accB.w += bB.w;
        *(float4*)(orow + iB) = accB;
    }
}

// ---------------- head mean + log_softmax: warp per node ----------------
__global__ void final_kernel(float* __restrict__ out)
{
    int v = (blockIdx.x * blockDim.x + threadIdx.x) >> 5;
    int lane = threadIdx.x & 31;
    if (v >= N_NODES) return;
    const float* row = g_out3 + (size_t)v * F3;
    int c0 = lane;          // < 47 always
    int c1 = lane + 32;     // valid if < 47
    bool has1 = c1 < NCLS;  // lane < 15
    float v0 = 0.25f * (row[0 * NCLS + c0] + row[1 * NCLS + c0] + row[2 * NCLS + c0] + row[3 * NCLS + c0]);
    float v1 = has1
        ? 0.25f * (row[0 * NCLS + c1] + row[1 * NCLS + c1] + row[2 * NCLS + c1] + row[3 * NCLS + c1])
        : -INFINITY;
    float m = fmaxf(v0, v1);
#pragma unroll
    for (int off = 16; off > 0; off >>= 1)
        m = fmaxf(m, __shfl_xor_sync(0xffffffffu, m, off));
    float s = __expf(v0 - m) + (has1 ? __expf(v1 - m) : 0.f);
#pragma unroll
    for (int off = 16; off > 0; off >>= 1)
        s += __shfl_xor_sync(0xffffffffu, s, off);
    float lse = m + logf(s);
    out[(size_t)v * NCLS + c0] = v0 - lse;
    if (has1) out[(size_t)v * NCLS + c1] = v1 - lse;
}

// ---------------- launch ----------------
extern "C" void kernel_launch(void* const* d_in, const int* in_sizes, int n_in,
                              void* d_out, int out_size)
{
    const float* x   = (const float*)d_in[0];
    const int*   src = (const int*)d_in[1];
    const int*   dst = (const int*)d_in[2];
    const float* W1  = (const float*)d_in[3];
    const float* al1 = (const float*)d_in[4];
    const float* ar1 = (const float*)d_in[5];
    const float* b1  = (const float*)d_in[6];
    const float* W2  = (const float*)d_in[7];
    const float* al2 = (const float*)d_in[8];
    const float* ar2 = (const float*)d_in[9];
    const float* b2  = (const float*)d_in[10];
    const float* W3  = (const float*)d_in[11];
    const float* al3 = (const float*)d_in[12];
    const float* ar3 = (const float*)d_in[13];
    const float* b3  = (const float*)d_in[14];
    float* out = (float*)d_out;

    float *feat, *hbuf, *out3;
    cudaGetSymbolAddress((void**)&feat, g_feat);
    cudaGetSymbolAddress((void**)&hbuf, g_h);
    cudaGetSymbolAddress((void**)&out3, g_out3);

    const int TB = 256;
    dim3 nodeGrid((N_NODES + TB - 1) / TB);
    dim3 edgeGrid((N_EDGES + TB - 1) / TB);
    dim3 warpNodeGrid((N_NODES * 32 + TB - 1) / TB);  // warp per node

    // CSR build (per launch; no caching allowed)
    zero_cnt_kernel<<<nodeGrid, TB>>>();
    hist_kernel<<<edgeGrid, TB>>>(dst);
    scan_kernel<<<1, 1024>>>();
    zero_cnt_kernel<<<nodeGrid, TB>>>();
    place_kernel<<<edgeGrid, TB>>>(src, dst);

    dim3 gemmBlk(256);
    // Layer 1: x[100000,256] @ W1[256,128]
    {
        dim3 grid((F1 + 63) / 64, (N_NODES + 63) / 64);
        sgemm_kernel<<<grid, gemmBlk>>>(x, W1, feat, N_NODES, IN_F, F1);
        elr_kernel<<<warpNodeGrid, TB>>>(al1, ar1, DHID, F1);
        mden_kernel<<<warpNodeGrid, TB>>>();
        agg128_kernel<<<warpNodeGrid, TB>>>(b1, hbuf, 1);
    }
    // Layer 2: h[100000,128] @ W2[128,128]
    {
        dim3 grid((F1 + 63) / 64, (N_NODES + 63) / 64);
        sgemm_kernel<<<grid, gemmBlk>>>(hbuf, W2, feat, N_NODES, F1, F1);
        elr_kernel<<<warpNodeGrid, TB>>>(al2, ar2, DHID, F1);
        mden_kernel<<<warpNodeGrid, TB>>>();
        agg128_kernel<<<warpNodeGrid, TB>>>(b2, hbuf, 1);
    }
    // Layer 3: h[100000,128] @ W3[128,188]
    {
        dim3 grid((F3 + 63) / 64, (N_NODES + 63) / 64);
        sgemm_kernel<<<grid, gemmBlk>>>(hbuf, W3, feat, N_NODES, F1, F3);
        elr_kernel<<<warpNodeGrid, TB>>>(al3, ar3, NCLS, F3);
        mden_kernel<<<warpNodeGrid, TB>>>();
        agg188_kernel<<<warpNodeGrid, TB>>>(b3, out3);
    }
    final_kernel<<<warpNodeGrid, TB>>>(out);
}